// round 16
// baseline (speedup 1.0000x reference)
#include <cuda_runtime.h>
#include <cuda_fp16.h>
#include <math.h>
#include <stdint.h>

#define SEQ   2048
#define EMB   512
#define HEADS 8
#define HDIM  64
#define BATCH 2
#define MTOT  (BATCH * SEQ)   // 4096
#define CHUNK 64
#define NCH   (SEQ / CHUNK)   // 32
#define NBH   (BATCH * HEADS) // 16

// ---------------- scratch (static device globals; no allocation) ----------------
__device__ float g_Q [MTOT * EMB];
__device__ float g_K [MTOT * EMB];
__device__ float g_V [MTOT * EMB];
__device__ float g_G [MTOT * EMB];
__device__ float g_A [NBH * NCH * HDIM * HDIM];
__device__ float g_S [NBH * NCH * HDIM * HDIM];
__device__ float g_sin[SEQ * 32];
__device__ float g_cos[SEQ * 32];
__device__ float g_hc [HEADS * 4];
// fp16, k-permuted operand copies (pairs (k,k+8) adjacent per 16-k group)
__device__ __half g_CXq[MTOT * EMB];
__device__ __half g_CXk[MTOT * EMB];
__device__ __half g_CXv[MTOT * EMB];
__device__ __half g_CX2[MTOT * EMB];
__device__ __half g_CW [5 * EMB * EMB];

// ---------------- operand convert+permute: float -> permuted fp16, 4 words/thread ----------------
__device__ __forceinline__ void cvt_rows_h4(const float* __restrict__ src,
                                            uint32_t* __restrict__ dst,
                                            int rows, int idx4)
{
    int row = idx4 >> 6;           // 64 threads per row
    if (row >= rows) return;
    int wk0 = (idx4 & 63) * 4;     // first of 4 consecutive output words
    uint32_t wout[4];
    #pragma unroll
    for (int p = 0; p < 4; p++) {
        int wk    = wk0 + p;
        int ktile = wk >> 4;
        int pos   = wk & 15;
        int g16   = pos >> 3;
        int q     = pos & 7;
        int j     = (q & 1) ? (q >> 1) + 4 : (q >> 1);
        int k     = ktile * 32 + g16 * 16 + 2 * j;
        const float* s = src + (size_t)row * EMB + k;
        __half2 h = __floats2half2_rn(s[0], s[1]);
        wout[p] = *(uint32_t*)&h;
    }
    *(uint4*)&dst[(size_t)row * 256 + wk0] = make_uint4(wout[0], wout[1], wout[2], wout[3]);
}

// job 0 also performs setup (rotary tables + per-head constants, fp64 once)
__global__ void __launch_bounds__(256) cvt_inputs_kernel(
    const float* __restrict__ q, const float* __restrict__ k,
    const float* __restrict__ v,
    const float* __restrict__ Wq, const float* __restrict__ Wk,
    const float* __restrict__ Wv, const float* __restrict__ Wg,
    const float* __restrict__ Wo)
{
    int idx4 = blockIdx.x * 256 + threadIdx.x;
    int job  = blockIdx.y;
    switch (job) {
        case 0: {
            int gid = idx4;
            if (gid < HEADS) {
                const double l0 = log(1.0 / 32.0), l1 = log(1.0 / 512.0);
                double gd = 1.0 - exp(l0 + (double)gid * (l1 - l0) / 7.0);
                g_hc[gid*4 + 0] = (float)gd;
                g_hc[gid*4 + 1] = (float)log(gd);
                g_hc[gid*4 + 2] = (float)pow(gd, (double)CHUNK);
                g_hc[gid*4 + 3] = (float)pow(gd, (double)(8 * CHUNK));
            }
            if (gid < SEQ * 32) {
                int n = gid >> 5;
                int i = gid & 31;
                double t     = (double)i / 31.0;
                double theta = pow(10000.0, -t);
                double ang   = (double)n * theta;
                g_sin[gid] = (float)sin(ang);
                g_cos[gid] = (float)cos(ang);
            }
            cvt_rows_h4(q,  (uint32_t*)g_CXq, MTOT, idx4);
            break;
        }
        case 1: cvt_rows_h4(k,  (uint32_t*)g_CXk, MTOT, idx4); break;
        case 2: cvt_rows_h4(v,  (uint32_t*)g_CXv, MTOT, idx4); break;
        case 3: cvt_rows_h4(Wq, (uint32_t*)(g_CW + 0*EMB*EMB), EMB, idx4); break;
        case 4: cvt_rows_h4(Wk, (uint32_t*)(g_CW + 1*EMB*EMB), EMB, idx4); break;
        case 5: cvt_rows_h4(Wv, (uint32_t*)(g_CW + 2*EMB*EMB), EMB, idx4); break;
        case 6: cvt_rows_h4(Wg, (uint32_t*)(g_CW + 3*EMB*EMB), EMB, idx4); break;
        default: cvt_rows_h4(Wo, (uint32_t*)(g_CW + 4*EMB*EMB), EMB, idx4); break;
    }
}

// ================= fp16 tensor-core GEMM (3-stage cp.async ring, 2 CTAs/SM) =================
__device__ __forceinline__ void cp16(uint32_t dst, const void* src) {
    asm volatile("cp.async.cg.shared.global [%0], [%1], 16;" :: "r"(dst), "l"(src));
}

__device__ __forceinline__ void mma_f16(float d[4],
    uint32_t a0, uint32_t a1, uint32_t a2, uint32_t a3,
    uint32_t b0, uint32_t b1)
{
    asm volatile(
        "mma.sync.aligned.m16n8k16.row.col.f32.f16.f16.f32 "
        "{%0,%1,%2,%3}, {%4,%5,%6,%7}, {%8,%9}, {%0,%1,%2,%3};"
        : "+f"(d[0]), "+f"(d[1]), "+f"(d[2]), "+f"(d[3])
        : "r"(a0), "r"(a1), "r"(a2), "r"(a3), "r"(b0), "r"(b1));
}

__device__ __forceinline__ void ldsm_x4(uint32_t (&r)[4], uint32_t addr) {
    asm volatile("ldmatrix.sync.aligned.m8n8.x4.shared.b16 {%0,%1,%2,%3}, [%4];"
                 : "=r"(r[0]), "=r"(r[1]), "=r"(r[2]), "=r"(r[3]) : "r"(addr));
}
__device__ __forceinline__ void ldsm_x2(uint32_t (&r)[2], uint32_t addr) {
    asm volatile("ldmatrix.sync.aligned.m8n8.x2.shared.b16 {%0,%1}, [%2];"
                 : "=r"(r[0]), "=r"(r[1]) : "r"(addr));
}

__device__ __forceinline__ void epi_pair(float& v0, float& v1, int row, int col,
                                         const float* __restrict__ bias, int mode)
{
    v0 += bias[col];
    v1 += bias[col + 1];
    if (mode == 1 || mode == 2) {
        int n = row & (SEQ - 1);
        int d = col & 63;
        float s = g_sin[n*32 + (d >> 1)];
        float c = g_cos[n*32 + (d >> 1)];
        float e = v0, o = v1;
        v0 = e*c - o*s;
        v1 = o*c + e*s;
        if (mode == 2) { v0 *= 0.125f; v1 *= 0.125f; }
    } else if (mode == 3) {
        v0 = v0 / (1.f + expf(-v0));
        v1 = v1 / (1.f + expf(-v1));
    }
}

__device__ __forceinline__ void gemm_tc(
    const __half* __restrict__ X, const __half* __restrict__ W,
    const float* __restrict__ bias, float* __restrict__ C, int mode)
{
    extern __shared__ uint32_t sm[];
    constexpr int SW  = 24;              // smem row stride (words)
    constexpr int HSW = 128 * SW;        // words per half (A or B)
    constexpr int STW = 2 * HSW;         // words per stage

    const int tid  = threadIdx.x;
    const int lane = tid & 31;
    const int warp = tid >> 5;
    const int wm   = (warp >> 2) * 64;
    const int wn   = (warp & 3) * 32;
    const int lr   = lane >> 2;
    const int lc   = lane & 3;
    const int m0   = blockIdx.y * 128;
    const int n0   = blockIdx.x * 128;

    const int rA = tid >> 2;
    const int ch = tid & 3;
    const __half* Xp = X + (size_t)(m0 + rA) * EMB + ch * 8;
    const __half* Wp = W + (size_t)(n0 + rA) * EMB + ch * 8;

    const uint32_t smbase = (uint32_t)__cvta_generic_to_shared(sm);
    const uint32_t doff   = ((uint32_t)(rA * SW) + ch * 4) * 4;

    float d[4][4][4];
    #pragma unroll
    for (int mi = 0; mi < 4; mi++)
        #pragma unroll
        for (int ni = 0; ni < 4; ni++)
            #pragma unroll
            for (int e = 0; e < 4; e++) d[mi][ni][e] = 0.f;

    auto issue = [&](int kt) {
        uint32_t As = smbase + (uint32_t)(kt % 3) * STW * 4;
        uint32_t Bs = As + HSW * 4;
        int kh = kt * 32;
        cp16(As + doff,           Xp + kh);
        cp16(As + doff + 64*SW*4, Xp + kh + (size_t)64 * EMB);
        cp16(Bs + doff,           Wp + kh);
        cp16(Bs + doff + 64*SW*4, Wp + kh + (size_t)64 * EMB);
        asm volatile("cp.async.commit_group;" ::: "memory");
    };

    issue(0);
    issue(1);

    for (int kt = 0; kt < 16; kt++) {
        if (kt < 15) asm volatile("cp.async.wait_group 1;" ::: "memory");
        else         asm volatile("cp.async.wait_group 0;" ::: "memory");
        __syncthreads();

        const uint32_t* As = sm + (kt % 3) * STW;
        const uint32_t* Bs = As + HSW;
        #pragma unroll
        for (int ks = 0; ks < 2; ks++) {
            const int kcol = 8*ks + 2*lc;
            uint2 a_lo[4], a_hi[4], bf[4];
            #pragma unroll
            for (int mi = 0; mi < 4; mi++) {
                a_lo[mi] = *(const uint2*)&As[(wm + mi*16 + lr)     * SW + kcol];
                a_hi[mi] = *(const uint2*)&As[(wm + mi*16 + 8 + lr) * SW + kcol];
            }
            #pragma unroll
            for (int ni = 0; ni < 4; ni++)
                bf[ni] = *(const uint2*)&Bs[(wn + ni*8 + lr) * SW + kcol];
            #pragma unroll
            for (int mi = 0; mi < 4; mi++)
                #pragma unroll
                for (int ni = 0; ni < 4; ni++)
                    mma_f16(d[mi][ni], a_lo[mi].x, a_hi[mi].x, a_lo[mi].y, a_hi[mi].y,
                            bf[ni].x, bf[ni].y);
        }
        if (kt < 14) issue(kt + 2);
    }

    #pragma unroll
    for (int mi = 0; mi < 4; mi++) {
        int row0 = m0 + wm + mi*16 + lr;
        #pragma unroll
        for (int ni = 0; ni < 4; ni++) {
            int col = n0 + wn + ni*8 + 2*lc;
            float v0 = d[mi][ni][0], v1 = d[mi][ni][1];
            epi_pair(v0, v1, row0, col, bias, mode);
            *(float2*)&C[(size_t)row0 * EMB + col] = make_float2(v0, v1);
            float v2 = d[mi][ni][2], v3 = d[mi][ni][3];
            epi_pair(v2, v3, row0 + 8, col, bias, mode);
            *(float2*)&C[(size_t)(row0 + 8) * EMB + col] = make_float2(v2, v3);
        }
    }
}

__global__ void __launch_bounds__(256) proj_kernel(
    const float* __restrict__ bq, const float* __restrict__ bk,
    const float* __restrict__ bv, const float* __restrict__ bg)
{
    int job = blockIdx.z;
    const __half* X; const __half* W; const float* B; float* O; int mode;
    if      (job == 0) { X = g_CXq; W = g_CW + 0*EMB*EMB; B = bq; O = g_Q; mode = 1; }
    else if (job == 1) { X = g_CXk; W = g_CW + 1*EMB*EMB; B = bk; O = g_K; mode = 2; }
    else if (job == 2) { X = g_CXv; W = g_CW + 2*EMB*EMB; B = bv; O = g_V; mode = 0; }
    else               { X = g_CXq; W = g_CW + 3*EMB*EMB; B = bg; O = g_G; mode = 3; }
    gemm_tc(X, W, B, O, mode);
}

__global__ void __launch_bounds__(256) out_kernel(
    const float* __restrict__ bo, float* __restrict__ out)
{
    gemm_tc(g_CX2, g_CW + 4*EMB*EMB, bo, out, 0);
}

// ================= chunkwise retention =================
// R1 (tensor-core): A[dk][dv] = sum_s K'[s][dk] * V[s][dv], K' = K * gamma^(C-s).
// smem: hKT[dk][s], hVT[dv][s] half (transposed, k=s contiguous).
// mma row.col: A-operand = hKT rows (m=dk), B-operand = hVT rows (n=dv).
// 8 warps as 4m x 2n; warp tile 16x32; 4 k-steps x 4 ni = 16 mmas/warp.
__global__ void __launch_bounds__(256) chunk_kv_kernel()
{
    __shared__ __half hKT[HDIM * CHUNK];   // [dk][s]
    __shared__ __half hVT[HDIM * CHUNK];   // [dv][s]

    const int tid  = threadIdx.x;
    const int lane = tid & 31;
    const int warp = tid >> 5;
    const int wm   = (warp >> 1) * 16;     // dk offset
    const int wn   = (warp & 1) * 32;      // dv offset
    const int c    = blockIdx.x;
    const int h    = blockIdx.y;
    const int b    = blockIdx.z;
    const int rowbase = b * SEQ + c * CHUNK;
    const int coff    = h * HDIM;

    const float lg = g_hc[h*4 + 1];

    // load + scale + convert + transpose
    for (int f = tid; f < CHUNK * 16; f += 256) {
        int s  = f >> 4;        // 0..63
        int d4 = f & 15;        // 0..15
        size_t gidx = (size_t)(rowbase + s) * EMB + coff + d4*4;
        float sc = expf(lg * (float)(CHUNK - s));
        float4 kv = *(const float4*)&g_K[gidx];
        hKT[(d4*4+0)*CHUNK + s] = __float2half_rn(kv.x * sc);
        hKT[(d4*4+1)*CHUNK + s] = __float2half_rn(kv.y * sc);
        hKT[(d4*4+2)*CHUNK + s] = __float2half_rn(kv.z * sc);
        hKT[(d4*4+3)*CHUNK + s] = __float2half_rn(kv.w * sc);
        float4 vv = *(const float4*)&g_V[gidx];
        hVT[(d4*4+0)*CHUNK + s] = __float2half_rn(vv.x);
        hVT[(d4*4+1)*CHUNK + s] = __float2half_rn(vv.y);
        hVT[(d4*4+2)*CHUNK + s] = __float2half_rn(vv.z);
        hVT[(d4*4+3)*CHUNK + s] = __float2half_rn(vv.w);
    }
    __syncthreads();

    const uint32_t aK = (uint32_t)__cvta_generic_to_shared(hKT);
    const uint32_t aV = (uint32_t)__cvta_generic_to_shared(hVT);

    float acc[4][4];
    #pragma unroll
    for (int ni = 0; ni < 4; ni++)
        #pragma unroll
        for (int e = 0; e < 4; e++) acc[ni][e] = 0.f;

    #pragma unroll
    for (int ks = 0; ks < 4; ks++) {
        const int k0 = ks * 16;
        uint32_t a[4];
        ldsm_x4(a, aK + (((wm + (lane & 15)) * CHUNK) + k0 + (lane >> 4) * 8) * 2);
        #pragma unroll
        for (int ni = 0; ni < 4; ni++) {
            uint32_t bfr[2];
            ldsm_x2(bfr, aV + (((wn + ni*8 + (lane & 7)) * CHUNK) + k0 + ((lane >> 3) & 1) * 8) * 2);
            mma_f16(acc[ni], a[0], a[1], a[2], a[3], bfr[0], bfr[1]);
        }
    }

    // store C fragments: rows wm+lr, wm+lr+8; cols wn+ni*8+2lc
    float* Ap = g_A + (size_t)(((b*HEADS + h)*NCH + c) * HDIM * HDIM);
    const int lr = lane >> 2;
    const int lc = lane & 3;
    #pragma unroll
    for (int ni = 0; ni < 4; ni++) {
        int col = wn + ni*8 + 2*lc;
        *(float2*)&Ap[(wm + lr)     * HDIM + col] = make_float2(acc[ni][0], acc[ni][1]);
        *(float2*)&Ap[(wm + lr + 8) * HDIM + col] = make_float2(acc[ni][2], acc[ni][3]);
    }
}

// R2: blocked parallel scan over chunks.
__global__ void __launch_bounds__(256) state_scan_kernel()
{
    __shared__ float Ts[4][64];

    const int tid  = threadIdx.x;
    const int e_lo = tid & 63;
    const int tq   = tid >> 6;
    const int bh   = blockIdx.x;
    const int eseg = blockIdx.y;
    const int e    = eseg * 64 + e_lo;
    const int h    = bh & (HEADS - 1);

    const float gc  = g_hc[h*4 + 2];
    const float gc8 = g_hc[h*4 + 3];

    const size_t base = (size_t)bh * NCH * HDIM * HDIM + e;
    const size_t toff = (size_t)(tq * 8) * HDIM * HDIM;

    float a[8];
    #pragma unroll
    for (int i = 0; i < 8; i++)
        a[i] = g_A[base + toff + (size_t)i * HDIM * HDIM];

    float p[8];
    float s = 0.f;
    #pragma unroll
    for (int i = 0; i < 8; i++) { p[i] = s; s = gc * s + a[i]; }
    Ts[tq][e_lo] = s;
    __syncthreads();

    float cr = 0.f;
    if (tq >= 1) cr = Ts[0][e_lo];
    if (tq >= 2) cr = gc8 * cr + Ts[1][e_lo];
    if (tq >= 3) cr = gc8 * cr + Ts[2][e_lo];

    float gpow = 1.f;
    #pragma unroll
    for (int i = 0; i < 8; i++) {
        g_S[base + toff + (size_t)i * HDIM * HDIM] = fmaf(gpow, cr, p[i]);
        gpow *= gc;
    }
}

// R3: intra-chunk + cross term via state, fused GroupNorm*gate.
// Epilogue writes fp16, k-permuted output directly to g_CX2.
__global__ void __launch_bounds__(256) retention_kernel()
{
    __shared__ float QsT[HDIM * CHUNK];
    __shared__ float KsT[HDIM * CHUNK];
    __shared__ float Vs [CHUNK * HDIM];
    __shared__ float Ss [HDIM * HDIM];

    const int tid = threadIdx.x;
    const int tx  = tid & 15;
    const int ty  = tid >> 4;
    const int c   = blockIdx.x;
    const int h   = blockIdx.y;
    const int b   = blockIdx.z;
    const int rowbase = b * SEQ + c * CHUNK;
    const int coff    = h * HDIM;

    const float gamma = g_hc[h*4 + 0];
    const float lg    = g_hc[h*4 + 1];
    float gi[4], gjv[4];
    gi[0]  = 1.f; gi[1] = gamma; gi[2] = gamma*gamma; gi[3] = gi[2]*gamma;
    float ginv = 1.f / gamma;
    gjv[0] = 1.f; gjv[1] = ginv; gjv[2] = ginv*ginv;  gjv[3] = gjv[2]*ginv;

    const float* Sp = g_S + (size_t)(((b*HEADS + h)*NCH + c) * HDIM * HDIM);
    for (int f = tid; f < CHUNK * 16; f += 256) {
        int s  = f & 63;
        int d4 = f >> 6;
        size_t gidx = (size_t)(rowbase + s) * EMB + coff + d4*4;
        float4 qv = *(const float4*)&g_Q[gidx];
        QsT[(d4*4+0)*CHUNK + s] = qv.x;
        QsT[(d4*4+1)*CHUNK + s] = qv.y;
        QsT[(d4*4+2)*CHUNK + s] = qv.z;
        QsT[(d4*4+3)*CHUNK + s] = qv.w;
        float4 kv = *(const float4*)&g_K[gidx];
        KsT[(d4*4+0)*CHUNK + s] = kv.x;
        KsT[(d4*4+1)*CHUNK + s] = kv.y;
        KsT[(d4*4+2)*CHUNK + s] = kv.z;
        KsT[(d4*4+3)*CHUNK + s] = kv.w;
        *(float4*)&Vs[s*HDIM + d4*4] = *(const float4*)&g_V[gidx];
        *(float4*)&Ss[f*4] = *(const float4*)&Sp[f*4];
    }
    __syncthreads();

    float sacc[4][4];
    #pragma unroll
    for (int i = 0; i < 4; i++)
        #pragma unroll
        for (int j = 0; j < 4; j++) sacc[i][j] = 0.f;
    #pragma unroll 8
    for (int d = 0; d < HDIM; d++) {
        float4 a  = *(const float4*)&QsT[d*CHUNK + ty*4];
        float4 bb = *(const float4*)&KsT[d*CHUNK + tx*4];
        float av[4] = {a.x, a.y, a.z, a.w};
        float bv[4] = {bb.x, bb.y, bb.z, bb.w};
        #pragma unroll
        for (int i = 0; i < 4; i++)
            #pragma unroll
            for (int j = 0; j < 4; j++)
                sacc[i][j] = fmaf(av[i], bv[j], sacc[i][j]);
    }
    {
        float d0 = expf(lg * (float)(ty*4 - tx*4));
        #pragma unroll
        for (int i = 0; i < 4; i++) {
            int n = ty*4 + i;
            #pragma unroll
            for (int j = 0; j < 4; j++) {
                int s = tx*4 + j;
                sacc[i][j] = (s <= n) ? sacc[i][j] * d0 * gi[i] * gjv[j] : 0.f;
            }
        }
    }
    __syncthreads();
    #pragma unroll
    for (int j = 0; j < 4; j++)
        *(float4*)&KsT[(tx*4+j)*CHUNK + ty*4] =
            make_float4(sacc[0][j], sacc[1][j], sacc[2][j], sacc[3][j]);
    __syncthreads();

    float oacc[4][4];
    #pragma unroll
    for (int i = 0; i < 4; i++)
        #pragma unroll
        for (int j = 0; j < 4; j++) oacc[i][j] = 0.f;
    #pragma unroll 8
    for (int s = 0; s < CHUNK; s++) {
        float4 a  = *(const float4*)&KsT[s*CHUNK + ty*4];
        float4 bb = *(const float4*)&Vs[s*HDIM + tx*4];
        float av[4] = {a.x, a.y, a.z, a.w};
        float bv[4] = {bb.x, bb.y, bb.z, bb.w};
        #pragma unroll
        for (int i = 0; i < 4; i++)
            #pragma unroll
            for (int j = 0; j < 4; j++)
                oacc[i][j] = fmaf(av[i], bv[j], oacc[i][j]);
    }

    {
        float cacc[4][4];
        #pragma unroll
        for (int i = 0; i < 4; i++)
            #pragma unroll
            for (int j = 0; j < 4; j++) cacc[i][j] = 0.f;
        #pragma unroll 8
        for (int d = 0; d < HDIM; d++) {
            float4 a  = *(const float4*)&QsT[d*CHUNK + ty*4];
            float4 bb = *(const float4*)&Ss[d*HDIM + tx*4];
            float av[4] = {a.x, a.y, a.z, a.w};
            float bv[4] = {bb.x, bb.y, bb.z, bb.w};
            #pragma unroll
            for (int i = 0; i < 4; i++)
                #pragma unroll
                for (int j = 0; j < 4; j++)
                    cacc[i][j] = fmaf(av[i], bv[j], cacc[i][j]);
        }
        #pragma unroll
        for (int i = 0; i < 4; i++) {
            float gq = expf(lg * (float)(ty*4 + i));
            #pragma unroll
            for (int j = 0; j < 4; j++)
                oacc[i][j] = fmaf(gq, cacc[i][j], oacc[i][j]);
        }
    }

    __syncthreads();
    #pragma unroll
    for (int i = 0; i < 4; i++)
        *(float4*)&KsT[(ty*4+i)*HDIM + tx*4] =
            make_float4(oacc[i][0], oacc[i][1], oacc[i][2], oacc[i][3]);
    __syncthreads();

    const int r = tid >> 2;
    const int p = tid & 3;
    float vals[16];
    float lsum = 0.f;
    #pragma unroll
    for (int j = 0; j < 16; j++) {
        vals[j] = KsT[r*HDIM + p*16 + j];
        lsum += vals[j];
    }
    lsum += __shfl_xor_sync(0xffffffffu, lsum, 1);
    lsum += __shfl_xor_sync(0xffffffffu, lsum, 2);
    float mean = lsum * (1.f / 64.f);
    float lsq = 0.f;
    #pragma unroll
    for (int j = 0; j < 16; j++) {
        float dd = vals[j] - mean;
        lsq += dd * dd;
    }
    lsq += __shfl_xor_sync(0xffffffffu, lsq, 1);
    lsq += __shfl_xor_sync(0xffffffffu, lsq, 2);
    float rstd = rsqrtf(lsq * (1.f / 64.f) + 1e-6f);

    const int n = c * CHUNK + r;
    const size_t rowoff = (size_t)(b * SEQ + n) * EMB;
    #pragma unroll
    for (int j = 0; j < 16; j++) {
        int col = coff + p*16 + j;
        float gte = g_G[rowoff + col];
        float v = (vals[j] - mean) * rstd * gte;
        int ktile = col >> 5;
        int k5    = col & 31;
        int g16   = k5 >> 4;
        int kk    = k5 & 15;
        int jw    = kk >> 1;
        int e     = kk & 1;
        int permw = g16*8 + ((jw < 4) ? 2*jw : 2*(jw-4)+1);
        g_CX2[rowoff + ktile*32 + permw*2 + e] = __float2half_rn(v);
    }
}

// ---------------- launch ----------------
extern "C" void kernel_launch(void* const* d_in, const int* in_sizes, int n_in,
                              void* d_out, int out_size)
{
    const float* query = (const float*)d_in[0];
    const float* kk    = (const float*)d_in[1];
    const float* vv    = (const float*)d_in[2];
    const float* Wq    = (const float*)d_in[3];
    const float* bq    = (const float*)d_in[4];
    const float* Wk    = (const float*)d_in[5];
    const float* bk    = (const float*)d_in[6];
    const float* Wv    = (const float*)d_in[7];
    const float* bv    = (const float*)d_in[8];
    const float* Wg    = (const float*)d_in[9];
    const float* bg    = (const float*)d_in[10];
    const float* Wo    = (const float*)d_in[11];
    const float* bo    = (const float*)d_in[12];
    float* out = (float*)d_out;

    const int SMEM_GEMM = 3 * 2 * 128 * 24 * 4;   // 73728 B -> 2 CTAs/SM
    cudaFuncSetAttribute(proj_kernel, cudaFuncAttributeMaxDynamicSharedMemorySize, SMEM_GEMM);
    cudaFuncSetAttribute(out_kernel,  cudaFuncAttributeMaxDynamicSharedMemorySize, SMEM_GEMM);

    dim3 cg(MTOT * 64 / 256, 8);          // 4 words/thread; job 0 also does setup
    cvt_inputs_kernel<<<cg, 256>>>(query, kk, vv, Wq, Wk, Wv, Wg, Wo);

    dim3 pg(4, 32, 4);
    proj_kernel<<<pg, 256, SMEM_GEMM>>>(bq, bk, bv, bg);

    dim3 ag(NCH, HEADS, BATCH);
    chunk_kv_kernel<<<ag, 256>>>();

    dim3 sg(NBH, 64);
    state_scan_kernel<<<sg, 256>>>();

    dim3 rg(NCH, HEADS, BATCH);
    retention_kernel<<<rg, 256>>>();

    dim3 og(4, 32, 1);
    out_kernel<<<og, 256, SMEM_GEMM>>>(bo, out);
}

// round 17
// speedup vs baseline: 1.0824x; 1.0824x over previous
#include <cuda_runtime.h>
#include <cuda_fp16.h>
#include <math.h>
#include <stdint.h>

#define SEQ   2048
#define EMB   512
#define HEADS 8
#define HDIM  64
#define BATCH 2
#define MTOT  (BATCH * SEQ)   // 4096
#define CHUNK 64
#define NCH   (SEQ / CHUNK)   // 32
#define NBH   (BATCH * HEADS) // 16

// ---------------- scratch (static device globals; no allocation) ----------------
__device__ float g_Q [MTOT * EMB];
__device__ float g_K [MTOT * EMB];
__device__ float g_V [MTOT * EMB];
__device__ float g_G [MTOT * EMB];
__device__ float g_A [NBH * NCH * HDIM * HDIM];
__device__ float g_S [NBH * NCH * HDIM * HDIM];
__device__ float g_sin[SEQ * 32];
__device__ float g_cos[SEQ * 32];
__device__ float g_hc [HEADS * 4];
// fp16, k-permuted operand copies (pairs (k,k+8) adjacent per 16-k group)
__device__ __half g_CXq[MTOT * EMB];
__device__ __half g_CXk[MTOT * EMB];
__device__ __half g_CXv[MTOT * EMB];
__device__ __half g_CX2[MTOT * EMB];
__device__ __half g_CW [5 * EMB * EMB];

// ---------------- operand convert+permute: float -> permuted fp16, 4 words/thread ----------------
__device__ __forceinline__ void cvt_rows_h4(const float* __restrict__ src,
                                            uint32_t* __restrict__ dst,
                                            int rows, int idx4)
{
    int row = idx4 >> 6;           // 64 threads per row
    if (row >= rows) return;
    int wk0 = (idx4 & 63) * 4;     // first of 4 consecutive output words
    uint32_t wout[4];
    #pragma unroll
    for (int p = 0; p < 4; p++) {
        int wk    = wk0 + p;
        int ktile = wk >> 4;
        int pos   = wk & 15;
        int g16   = pos >> 3;
        int q     = pos & 7;
        int j     = (q & 1) ? (q >> 1) + 4 : (q >> 1);
        int k     = ktile * 32 + g16 * 16 + 2 * j;
        const float* s = src + (size_t)row * EMB + k;
        __half2 h = __floats2half2_rn(s[0], s[1]);
        wout[p] = *(uint32_t*)&h;
    }
    *(uint4*)&dst[(size_t)row * 256 + wk0] = make_uint4(wout[0], wout[1], wout[2], wout[3]);
}

// job 0 also performs setup (rotary tables + per-head constants, fp64 once)
__global__ void __launch_bounds__(256) cvt_inputs_kernel(
    const float* __restrict__ q, const float* __restrict__ k,
    const float* __restrict__ v,
    const float* __restrict__ Wq, const float* __restrict__ Wk,
    const float* __restrict__ Wv, const float* __restrict__ Wg,
    const float* __restrict__ Wo)
{
    int idx4 = blockIdx.x * 256 + threadIdx.x;
    int job  = blockIdx.y;
    switch (job) {
        case 0: {
            int gid = idx4;
            if (gid < HEADS) {
                const double l0 = log(1.0 / 32.0), l1 = log(1.0 / 512.0);
                double gd = 1.0 - exp(l0 + (double)gid * (l1 - l0) / 7.0);
                g_hc[gid*4 + 0] = (float)gd;
                g_hc[gid*4 + 1] = (float)log(gd);
                g_hc[gid*4 + 2] = (float)pow(gd, (double)CHUNK);
                g_hc[gid*4 + 3] = (float)pow(gd, (double)(8 * CHUNK));
            }
            if (gid < SEQ * 32) {
                int n = gid >> 5;
                int i = gid & 31;
                double t     = (double)i / 31.0;
                double theta = pow(10000.0, -t);
                double ang   = (double)n * theta;
                g_sin[gid] = (float)sin(ang);
                g_cos[gid] = (float)cos(ang);
            }
            cvt_rows_h4(q,  (uint32_t*)g_CXq, MTOT, idx4);
            break;
        }
        case 1: cvt_rows_h4(k,  (uint32_t*)g_CXk, MTOT, idx4); break;
        case 2: cvt_rows_h4(v,  (uint32_t*)g_CXv, MTOT, idx4); break;
        case 3: cvt_rows_h4(Wq, (uint32_t*)(g_CW + 0*EMB*EMB), EMB, idx4); break;
        case 4: cvt_rows_h4(Wk, (uint32_t*)(g_CW + 1*EMB*EMB), EMB, idx4); break;
        case 5: cvt_rows_h4(Wv, (uint32_t*)(g_CW + 2*EMB*EMB), EMB, idx4); break;
        case 6: cvt_rows_h4(Wg, (uint32_t*)(g_CW + 3*EMB*EMB), EMB, idx4); break;
        default: cvt_rows_h4(Wo, (uint32_t*)(g_CW + 4*EMB*EMB), EMB, idx4); break;
    }
}

// ================= fp16 tensor-core GEMM (3-stage cp.async ring, 2 CTAs/SM) =================
__device__ __forceinline__ void cp16(uint32_t dst, const void* src) {
    asm volatile("cp.async.cg.shared.global [%0], [%1], 16;" :: "r"(dst), "l"(src));
}

__device__ __forceinline__ void mma_f16(float d[4],
    uint32_t a0, uint32_t a1, uint32_t a2, uint32_t a3,
    uint32_t b0, uint32_t b1)
{
    asm volatile(
        "mma.sync.aligned.m16n8k16.row.col.f32.f16.f16.f32 "
        "{%0,%1,%2,%3}, {%4,%5,%6,%7}, {%8,%9}, {%0,%1,%2,%3};"
        : "+f"(d[0]), "+f"(d[1]), "+f"(d[2]), "+f"(d[3])
        : "r"(a0), "r"(a1), "r"(a2), "r"(a3), "r"(b0), "r"(b1));
}

__device__ __forceinline__ void ldsm_x4_t(uint32_t (&r)[4], uint32_t addr) {
    asm volatile("ldmatrix.sync.aligned.m8n8.x4.trans.shared.b16 {%0,%1,%2,%3}, [%4];"
                 : "=r"(r[0]), "=r"(r[1]), "=r"(r[2]), "=r"(r[3]) : "r"(addr));
}
__device__ __forceinline__ void ldsm_x2_t(uint32_t (&r)[2], uint32_t addr) {
    asm volatile("ldmatrix.sync.aligned.m8n8.x2.trans.shared.b16 {%0,%1}, [%2];"
                 : "=r"(r[0]), "=r"(r[1]) : "r"(addr));
}

__device__ __forceinline__ void epi_pair(float& v0, float& v1, int row, int col,
                                         const float* __restrict__ bias, int mode)
{
    v0 += bias[col];
    v1 += bias[col + 1];
    if (mode == 1 || mode == 2) {
        int n = row & (SEQ - 1);
        int d = col & 63;
        float s = g_sin[n*32 + (d >> 1)];
        float c = g_cos[n*32 + (d >> 1)];
        float e = v0, o = v1;
        v0 = e*c - o*s;
        v1 = o*c + e*s;
        if (mode == 2) { v0 *= 0.125f; v1 *= 0.125f; }
    } else if (mode == 3) {
        v0 = v0 / (1.f + expf(-v0));
        v1 = v1 / (1.f + expf(-v1));
    }
}

__device__ __forceinline__ void gemm_tc(
    const __half* __restrict__ X, const __half* __restrict__ W,
    const float* __restrict__ bias, float* __restrict__ C, int mode)
{
    extern __shared__ uint32_t sm[];
    constexpr int SW  = 24;              // smem row stride (words)
    constexpr int HSW = 128 * SW;        // words per half (A or B)
    constexpr int STW = 2 * HSW;         // words per stage

    const int tid  = threadIdx.x;
    const int lane = tid & 31;
    const int warp = tid >> 5;
    const int wm   = (warp >> 2) * 64;
    const int wn   = (warp & 3) * 32;
    const int lr   = lane >> 2;
    const int lc   = lane & 3;
    const int m0   = blockIdx.y * 128;
    const int n0   = blockIdx.x * 128;

    const int rA = tid >> 2;
    const int ch = tid & 3;
    const __half* Xp = X + (size_t)(m0 + rA) * EMB + ch * 8;
    const __half* Wp = W + (size_t)(n0 + rA) * EMB + ch * 8;

    const uint32_t smbase = (uint32_t)__cvta_generic_to_shared(sm);
    const uint32_t doff   = ((uint32_t)(rA * SW) + ch * 4) * 4;

    float d[4][4][4];
    #pragma unroll
    for (int mi = 0; mi < 4; mi++)
        #pragma unroll
        for (int ni = 0; ni < 4; ni++)
            #pragma unroll
            for (int e = 0; e < 4; e++) d[mi][ni][e] = 0.f;

    auto issue = [&](int kt) {
        uint32_t As = smbase + (uint32_t)(kt % 3) * STW * 4;
        uint32_t Bs = As + HSW * 4;
        int kh = kt * 32;
        cp16(As + doff,           Xp + kh);
        cp16(As + doff + 64*SW*4, Xp + kh + (size_t)64 * EMB);
        cp16(Bs + doff,           Wp + kh);
        cp16(Bs + doff + 64*SW*4, Wp + kh + (size_t)64 * EMB);
        asm volatile("cp.async.commit_group;" ::: "memory");
    };

    issue(0);
    issue(1);

    for (int kt = 0; kt < 16; kt++) {
        if (kt < 15) asm volatile("cp.async.wait_group 1;" ::: "memory");
        else         asm volatile("cp.async.wait_group 0;" ::: "memory");
        __syncthreads();

        const uint32_t* As = sm + (kt % 3) * STW;
        const uint32_t* Bs = As + HSW;
        #pragma unroll
        for (int ks = 0; ks < 2; ks++) {
            const int kcol = 8*ks + 2*lc;
            uint2 a_lo[4], a_hi[4], bf[4];
            #pragma unroll
            for (int mi = 0; mi < 4; mi++) {
                a_lo[mi] = *(const uint2*)&As[(wm + mi*16 + lr)     * SW + kcol];
                a_hi[mi] = *(const uint2*)&As[(wm + mi*16 + 8 + lr) * SW + kcol];
            }
            #pragma unroll
            for (int ni = 0; ni < 4; ni++)
                bf[ni] = *(const uint2*)&Bs[(wn + ni*8 + lr) * SW + kcol];
            #pragma unroll
            for (int mi = 0; mi < 4; mi++)
                #pragma unroll
                for (int ni = 0; ni < 4; ni++)
                    mma_f16(d[mi][ni], a_lo[mi].x, a_hi[mi].x, a_lo[mi].y, a_hi[mi].y,
                            bf[ni].x, bf[ni].y);
        }
        if (kt < 14) issue(kt + 2);
    }

    #pragma unroll
    for (int mi = 0; mi < 4; mi++) {
        int row0 = m0 + wm + mi*16 + lr;
        #pragma unroll
        for (int ni = 0; ni < 4; ni++) {
            int col = n0 + wn + ni*8 + 2*lc;
            float v0 = d[mi][ni][0], v1 = d[mi][ni][1];
            epi_pair(v0, v1, row0, col, bias, mode);
            *(float2*)&C[(size_t)row0 * EMB + col] = make_float2(v0, v1);
            float v2 = d[mi][ni][2], v3 = d[mi][ni][3];
            epi_pair(v2, v3, row0 + 8, col, bias, mode);
            *(float2*)&C[(size_t)(row0 + 8) * EMB + col] = make_float2(v2, v3);
        }
    }
}

__global__ void __launch_bounds__(256) proj_kernel(
    const float* __restrict__ bq, const float* __restrict__ bk,
    const float* __restrict__ bv, const float* __restrict__ bg)
{
    int job = blockIdx.z;
    const __half* X; const __half* W; const float* B; float* O; int mode;
    if      (job == 0) { X = g_CXq; W = g_CW + 0*EMB*EMB; B = bq; O = g_Q; mode = 1; }
    else if (job == 1) { X = g_CXk; W = g_CW + 1*EMB*EMB; B = bk; O = g_K; mode = 2; }
    else if (job == 2) { X = g_CXv; W = g_CW + 2*EMB*EMB; B = bv; O = g_V; mode = 0; }
    else               { X = g_CXq; W = g_CW + 3*EMB*EMB; B = bg; O = g_G; mode = 3; }
    gemm_tc(X, W, B, O, mode);
}

__global__ void __launch_bounds__(256) out_kernel(
    const float* __restrict__ bo, float* __restrict__ out)
{
    gemm_tc(g_CX2, g_CW + 4*EMB*EMB, bo, out, 0);
}

// ================= chunkwise retention =================
// R1 (tensor-core): A[dk][dv] = sum_s K'[s][dk] * V[s][dv], K' = K * gamma^(C-s).
// smem: hK[s][dk], hV[s][dv] half, NATURAL layout (coalesced fill, same pattern
// as the proven scalar version), padded stride 72 halves -> conflict-free
// ldmatrix.trans row reads. Fragments via ldmatrix .trans (K-major -> row.col).
// 8 warps as 4m x 2n; warp tile 16x32; 4 k-steps x 4 ni = 16 mmas/warp.
__global__ void __launch_bounds__(256) chunk_kv_kernel()
{
    constexpr int SWc = CHUNK + 8;   // 72 halves = 144 B stride
    __shared__ __half hK[CHUNK * SWc];
    __shared__ __half hV[CHUNK * SWc];

    const int tid  = threadIdx.x;
    const int lane = tid & 31;
    const int warp = tid >> 5;
    const int wm   = (warp >> 1) * 16;     // dk offset
    const int wn   = (warp & 1) * 32;      // dv offset
    const int c    = blockIdx.x;
    const int h    = blockIdx.y;
    const int b    = blockIdx.z;
    const int rowbase = b * SEQ + c * CHUNK;
    const int coff    = h * HDIM;

    const float lg = g_hc[h*4 + 1];

    // fill: natural [s][d] layout, 8B stores (same access shape as R15 fill)
    for (int f = tid; f < CHUNK * 16; f += 256) {
        int s  = f >> 4;        // 0..63
        int d4 = f & 15;        // 0..15
        size_t gidx = (size_t)(rowbase + s) * EMB + coff + d4*4;
        float sc = expf(lg * (float)(CHUNK - s));
        float4 kv = *(const float4*)&g_K[gidx];
        __half2 k01 = __floats2half2_rn(kv.x * sc, kv.y * sc);
        __half2 k23 = __floats2half2_rn(kv.z * sc, kv.w * sc);
        *(uint2*)&hK[s*SWc + d4*4] = make_uint2(*(uint32_t*)&k01, *(uint32_t*)&k23);
        float4 vv = *(const float4*)&g_V[gidx];
        __half2 v01 = __floats2half2_rn(vv.x, vv.y);
        __half2 v23 = __floats2half2_rn(vv.z, vv.w);
        *(uint2*)&hV[s*SWc + d4*4] = make_uint2(*(uint32_t*)&v01, *(uint32_t*)&v23);
    }
    __syncthreads();

    const uint32_t aK = (uint32_t)__cvta_generic_to_shared(hK);
    const uint32_t aV = (uint32_t)__cvta_generic_to_shared(hV);

    float acc[4][4];
    #pragma unroll
    for (int ni = 0; ni < 4; ni++)
        #pragma unroll
        for (int e = 0; e < 4; e++) acc[ni][e] = 0.f;

    // A trans addresses: lane groups 0-7->r0(m wm..+7,k k0..+7), 8-15->r1(m+8),
    // 16-23->r2(k+8), 24-31->r3(m+8,k+8); stored rows = k (s), cols = m (dk).
    const int ag = lane >> 3;        // 0..3
    const int al = lane & 7;
    const int arow_off = (ag >> 1) * 8 + al;       // s offset within 16-k step
    const int acol     = wm + (ag & 1) * 8;        // dk column
    // B trans addresses (x2, lanes 0-15): b0 rows k0..+7, b1 rows k0+8..+15.
    const int brow_off = ((lane >> 3) & 1) * 8 + (lane & 7);

    #pragma unroll
    for (int ks = 0; ks < 4; ks++) {
        const int k0 = ks * 16;
        uint32_t a[4];
        ldsm_x4_t(a, aK + (uint32_t)((k0 + arow_off) * SWc + acol) * 2);
        #pragma unroll
        for (int ni = 0; ni < 4; ni++) {
            uint32_t bfr[2];
            ldsm_x2_t(bfr, aV + (uint32_t)((k0 + brow_off) * SWc + wn + ni*8) * 2);
            mma_f16(acc[ni], a[0], a[1], a[2], a[3], bfr[0], bfr[1]);
        }
    }

    // store C fragments: rows wm+lr, wm+lr+8; cols wn+ni*8+2lc  (verified in R16)
    float* Ap = g_A + (size_t)(((b*HEADS + h)*NCH + c) * HDIM * HDIM);
    const int lr = lane >> 2;
    const int lc = lane & 3;
    #pragma unroll
    for (int ni = 0; ni < 4; ni++) {
        int col = wn + ni*8 + 2*lc;
        *(float2*)&Ap[(wm + lr)     * HDIM + col] = make_float2(acc[ni][0], acc[ni][1]);
        *(float2*)&Ap[(wm + lr + 8) * HDIM + col] = make_float2(acc[ni][2], acc[ni][3]);
    }
}

// R2: blocked parallel scan over chunks.
__global__ void __launch_bounds__(256) state_scan_kernel()
{
    __shared__ float Ts[4][64];

    const int tid  = threadIdx.x;
    const int e_lo = tid & 63;
    const int tq   = tid >> 6;
    const int bh   = blockIdx.x;
    const int eseg = blockIdx.y;
    const int e    = eseg * 64 + e_lo;
    const int h    = bh & (HEADS - 1);

    const float gc  = g_hc[h*4 + 2];
    const float gc8 = g_hc[h*4 + 3];

    const size_t base = (size_t)bh * NCH * HDIM * HDIM + e;
    const size_t toff = (size_t)(tq * 8) * HDIM * HDIM;

    float a[8];
    #pragma unroll
    for (int i = 0; i < 8; i++)
        a[i] = g_A[base + toff + (size_t)i * HDIM * HDIM];

    float p[8];
    float s = 0.f;
    #pragma unroll
    for (int i = 0; i < 8; i++) { p[i] = s; s = gc * s + a[i]; }
    Ts[tq][e_lo] = s;
    __syncthreads();

    float cr = 0.f;
    if (tq >= 1) cr = Ts[0][e_lo];
    if (tq >= 2) cr = gc8 * cr + Ts[1][e_lo];
    if (tq >= 3) cr = gc8 * cr + Ts[2][e_lo];

    float gpow = 1.f;
    #pragma unroll
    for (int i = 0; i < 8; i++) {
        g_S[base + toff + (size_t)i * HDIM * HDIM] = fmaf(gpow, cr, p[i]);
        gpow *= gc;
    }
}

// R3: intra-chunk + cross term via state, fused GroupNorm*gate.
// Epilogue writes fp16, k-permuted output directly to g_CX2.
__global__ void __launch_bounds__(256) retention_kernel()
{
    __shared__ float QsT[HDIM * CHUNK];
    __shared__ float KsT[HDIM * CHUNK];
    __shared__ float Vs [CHUNK * HDIM];
    __shared__ float Ss [HDIM * HDIM];

    const int tid = threadIdx.x;
    const int tx  = tid & 15;
    const int ty  = tid >> 4;
    const int c   = blockIdx.x;
    const int h   = blockIdx.y;
    const int b   = blockIdx.z;
    const int rowbase = b * SEQ + c * CHUNK;
    const int coff    = h * HDIM;

    const float gamma = g_hc[h*4 + 0];
    const float lg    = g_hc[h*4 + 1];
    float gi[4], gjv[4];
    gi[0]  = 1.f; gi[1] = gamma; gi[2] = gamma*gamma; gi[3] = gi[2]*gamma;
    float ginv = 1.f / gamma;
    gjv[0] = 1.f; gjv[1] = ginv; gjv[2] = ginv*ginv;  gjv[3] = gjv[2]*ginv;

    const float* Sp = g_S + (size_t)(((b*HEADS + h)*NCH + c) * HDIM * HDIM);
    for (int f = tid; f < CHUNK * 16; f += 256) {
        int s  = f & 63;
        int d4 = f >> 6;
        size_t gidx = (size_t)(rowbase + s) * EMB + coff + d4*4;
        float4 qv = *(const float4*)&g_Q[gidx];
        QsT[(d4*4+0)*CHUNK + s] = qv.x;
        QsT[(d4*4+1)*CHUNK + s] = qv.y;
        QsT[(d4*4+2)*CHUNK + s] = qv.z;
        QsT[(d4*4+3)*CHUNK + s] = qv.w;
        float4 kv = *(const float4*)&g_K[gidx];
        KsT[(d4*4+0)*CHUNK + s] = kv.x;
        KsT[(d4*4+1)*CHUNK + s] = kv.y;
        KsT[(d4*4+2)*CHUNK + s] = kv.z;
        KsT[(d4*4+3)*CHUNK + s] = kv.w;
        *(float4*)&Vs[s*HDIM + d4*4] = *(const float4*)&g_V[gidx];
        *(float4*)&Ss[f*4] = *(const float4*)&Sp[f*4];
    }
    __syncthreads();

    float sacc[4][4];
    #pragma unroll
    for (int i = 0; i < 4; i++)
        #pragma unroll
        for (int j = 0; j < 4; j++) sacc[i][j] = 0.f;
    #pragma unroll 8
    for (int d = 0; d < HDIM; d++) {
        float4 a  = *(const float4*)&QsT[d*CHUNK + ty*4];
        float4 bb = *(const float4*)&KsT[d*CHUNK + tx*4];
        float av[4] = {a.x, a.y, a.z, a.w};
        float bv[4] = {bb.x, bb.y, bb.z, bb.w};
        #pragma unroll
        for (int i = 0; i < 4; i++)
            #pragma unroll
            for (int j = 0; j < 4; j++)
                sacc[i][j] = fmaf(av[i], bv[j], sacc[i][j]);
    }
    {
        float d0 = expf(lg * (float)(ty*4 - tx*4));
        #pragma unroll
        for (int i = 0; i < 4; i++) {
            int n = ty*4 + i;
            #pragma unroll
            for (int j = 0; j < 4; j++) {
                int s = tx*4 + j;
                sacc[i][j] = (s <= n) ? sacc[i][j] * d0 * gi[i] * gjv[j] : 0.f;
            }
        }
    }
    __syncthreads();
    #pragma unroll
    for (int j = 0; j < 4; j++)
        *(float4*)&KsT[(tx*4+j)*CHUNK + ty*4] =
            make_float4(sacc[0][j], sacc[1][j], sacc[2][j], sacc[3][j]);
    __syncthreads();

    float oacc[4][4];
    #pragma unroll
    for (int i = 0; i < 4; i++)
        #pragma unroll
        for (int j = 0; j < 4; j++) oacc[i][j] = 0.f;
    #pragma unroll 8
    for (int s = 0; s < CHUNK; s++) {
        float4 a  = *(const float4*)&KsT[s*CHUNK + ty*4];
        float4 bb = *(const float4*)&Vs[s*HDIM + tx*4];
        float av[4] = {a.x, a.y, a.z, a.w};
        float bv[4] = {bb.x, bb.y, bb.z, bb.w};
        #pragma unroll
        for (int i = 0; i < 4; i++)
            #pragma unroll
            for (int j = 0; j < 4; j++)
                oacc[i][j] = fmaf(av[i], bv[j], oacc[i][j]);
    }

    {
        float cacc[4][4];
        #pragma unroll
        for (int i = 0; i < 4; i++)
            #pragma unroll
            for (int j = 0; j < 4; j++) cacc[i][j] = 0.f;
        #pragma unroll 8
        for (int d = 0; d < HDIM; d++) {
            float4 a  = *(const float4*)&QsT[d*CHUNK + ty*4];
            float4 bb = *(const float4*)&Ss[d*HDIM + tx*4];
            float av[4] = {a.x, a.y, a.z, a.w};
            float bv[4] = {bb.x, bb.y, bb.z, bb.w};
            #pragma unroll
            for (int i = 0; i < 4; i++)
                #pragma unroll
                for (int j = 0; j < 4; j++)
                    cacc[i][j] = fmaf(av[i], bv[j], cacc[i][j]);
        }
        #pragma unroll
        for (int i = 0; i < 4; i++) {
            float gq = expf(lg * (float)(ty*4 + i));
            #pragma unroll
            for (int j = 0; j < 4; j++)
                oacc[i][j] = fmaf(gq, cacc[i][j], oacc[i][j]);
        }
    }

    __syncthreads();
    #pragma unroll
    for (int i = 0; i < 4; i++)
        *(float4*)&KsT[(ty*4+i)*HDIM + tx*4] =
            make_float4(oacc[i][0], oacc[i][1], oacc[i][2], oacc[i][3]);
    __syncthreads();

    const int r = tid >> 2;
    const int p = tid & 3;
    float vals[16];
    float lsum = 0.f;
    #pragma unroll
    for (int j = 0; j < 16; j++) {
        vals[j] = KsT[r*HDIM + p*16 + j];
        lsum += vals[j];
    }
    lsum += __shfl_xor_sync(0xffffffffu, lsum, 1);
    lsum += __shfl_xor_sync(0xffffffffu, lsum, 2);
    float mean = lsum * (1.f / 64.f);
    float lsq = 0.f;
    #pragma unroll
    for (int j = 0; j < 16; j++) {
        float dd = vals[j] - mean;
        lsq += dd * dd;
    }
    lsq += __shfl_xor_sync(0xffffffffu, lsq, 1);
    lsq += __shfl_xor_sync(0xffffffffu, lsq, 2);
    float rstd = rsqrtf(lsq * (1.f / 64.f) + 1e-6f);

    const int n = c * CHUNK + r;
    const size_t rowoff = (size_t)(b * SEQ + n) * EMB;
    #pragma unroll
    for (int j = 0; j < 16; j++) {
        int col = coff + p*16 + j;
        float gte = g_G[rowoff + col];
        float v = (vals[j] - mean) * rstd * gte;
        int ktile = col >> 5;
        int k5    = col & 31;
        int g16   = k5 >> 4;
        int kk    = k5 & 15;
        int jw    = kk >> 1;
        int e     = kk & 1;
        int permw = g16*8 + ((jw < 4) ? 2*jw : 2*(jw-4)+1);
        g_CX2[rowoff + ktile*32 + permw*2 + e] = __float2half_rn(v);
    }
}

// ---------------- launch ----------------
extern "C" void kernel_launch(void* const* d_in, const int* in_sizes, int n_in,
                              void* d_out, int out_size)
{
    const float* query = (const float*)d_in[0];
    const float* kk    = (const float*)d_in[1];
    const float* vv    = (const float*)d_in[2];
    const float* Wq    = (const float*)d_in[3];
    const float* bq    = (const float*)d_in[4];
    const float* Wk    = (const float*)d_in[5];
    const float* bk    = (const float*)d_in[6];
    const float* Wv    = (const float*)d_in[7];
    const float* bv    = (const float*)d_in[8];
    const float* Wg    = (const float*)d_in[9];
    const float* bg    = (const float*)d_in[10];
    const float* Wo    = (const float*)d_in[11];
    const float* bo    = (const float*)d_in[12];
    float* out = (float*)d_out;

    const int SMEM_GEMM = 3 * 2 * 128 * 24 * 4;   // 73728 B -> 2 CTAs/SM
    cudaFuncSetAttribute(proj_kernel, cudaFuncAttributeMaxDynamicSharedMemorySize, SMEM_GEMM);
    cudaFuncSetAttribute(out_kernel,  cudaFuncAttributeMaxDynamicSharedMemorySize, SMEM_GEMM);

    dim3 cg(MTOT * 64 / 256, 8);          // 4 words/thread; job 0 also does setup
    cvt_inputs_kernel<<<cg, 256>>>(query, kk, vv, Wq, Wk, Wv, Wg, Wo);

    dim3 pg(4, 32, 4);
    proj_kernel<<<pg, 256, SMEM_GEMM>>>(bq, bk, bv, bg);

    dim3 ag(NCH, HEADS, BATCH);
    chunk_kv_kernel<<<ag, 256>>>();

    dim3 sg(NBH, 64);
    state_scan_kernel<<<sg, 256>>>();

    dim3 rg(NCH, HEADS, BATCH);
    retention_kernel<<<rg, 256>>>();

    dim3 og(4, 32, 1);
    out_kernel<<<og, 256, SMEM_GEMM>>>(bo, out);
}